// round 6
// baseline (speedup 1.0000x reference)
#include <cuda_runtime.h>
#include <cuda_bf16.h>
#include <math.h>
#include <stdint.h>

// Problem shape (fixed by setup_inputs)
#define N_FEAT  32768
#define M_PROTO 2048
#define K_DIM   512

// ---------------------------------------------------------------------------
// Static device scratch (no cudaMalloc allowed)
// gXhi32: tf32-valued fp32, k-permuted per 8 (phys j = logical {0,4,1,5,2,6,3,7})
// gXhibf/gXlobf: bf16 hi/lo, pair-permuted per 8 pairs (same perm on pair idx)
// ---------------------------------------------------------------------------
__device__ float         gAhi32[(size_t)N_FEAT * K_DIM];
__device__ float         gBhi32[(size_t)M_PROTO * K_DIM];
__device__ __nv_bfloat16 gAhibf[(size_t)N_FEAT * K_DIM];
__device__ __nv_bfloat16 gAlobf[(size_t)N_FEAT * K_DIM];
__device__ __nv_bfloat16 gBhibf[(size_t)M_PROTO * K_DIM];
__device__ __nv_bfloat16 gBlobf[(size_t)M_PROTO * K_DIM];
__device__ float g_psq10[M_PROTO];      // 10 * ||p_m||^2

// ---------------------------------------------------------------------------
__device__ __forceinline__ uint32_t smem_u32(const void* p) {
    uint32_t a;
    asm("{ .reg .u64 t; cvta.to.shared.u64 t, %1; cvt.u32.u64 %0, t; }" : "=r"(a) : "l"(p));
    return a;
}
#define CP_ASYNC16(dst, src) \
    asm volatile("cp.async.cg.shared.global [%0], [%1], 16;" :: "r"(dst), "l"(src) : "memory")
#define CP_COMMIT() asm volatile("cp.async.commit_group;" ::: "memory")
#define CP_WAIT(n)  asm volatile("cp.async.wait_group %0;" :: "n"(n) : "memory")

__device__ __forceinline__ uint32_t f2tf32(float x) {
    uint32_t r;
    asm("cvt.rna.tf32.f32 %0, %1;" : "=r"(r) : "f"(x));
    return r;
}

// mma.sync m16n8k8 tf32 (sm_80 baseline -> legal on plain sm_100)
__device__ __forceinline__ void mma_tf32(float* d,
                                         uint32_t a0, uint32_t a1, uint32_t a2, uint32_t a3,
                                         uint32_t b0, uint32_t b1) {
    asm volatile(
        "mma.sync.aligned.m16n8k8.row.col.f32.tf32.tf32.f32 "
        "{%0,%1,%2,%3}, {%4,%5,%6,%7}, {%8,%9}, {%0,%1,%2,%3};"
        : "+f"(d[0]), "+f"(d[1]), "+f"(d[2]), "+f"(d[3])
        : "r"(a0), "r"(a1), "r"(a2), "r"(a3), "r"(b0), "r"(b1));
}

// mma.sync m16n8k16 bf16 (sm_80 baseline)
__device__ __forceinline__ void mma_bf16(float* d,
                                         uint32_t a0, uint32_t a1, uint32_t a2, uint32_t a3,
                                         uint32_t b0, uint32_t b1) {
    asm volatile(
        "mma.sync.aligned.m16n8k16.row.col.f32.bf16.bf16.f32 "
        "{%0,%1,%2,%3}, {%4,%5,%6,%7}, {%8,%9}, {%0,%1,%2,%3};"
        : "+f"(d[0]), "+f"(d[1]), "+f"(d[2]), "+f"(d[3])
        : "r"(a0), "r"(a1), "r"(a2), "r"(a3), "r"(b0), "r"(b1));
}

// fp32 tile smem index: 16 words/row + XOR granule swizzle (conflict-free)
__device__ __forceinline__ int idx32(int row, int kb) {
    return row * 16 + ((((kb >> 2) ^ row) & 3) << 2) + (kb & 3);
}

// ---------------------------------------------------------------------------
// Split fp32 -> tf32 hi (fp32, permuted per 8) + bf16(hi), bf16(lo)
// (pair-permuted per 8 pairs). One thread = 16 consecutive k of one row.
// ---------------------------------------------------------------------------
__global__ void split_kernel(const float* __restrict__ src, int ngroups, int which) {
    float*         hi32 = which ? gBhi32 : gAhi32;
    __nv_bfloat16* hibf = which ? gBhibf : gAhibf;
    __nv_bfloat16* lobf = which ? gBlobf : gAlobf;
    int g = blockIdx.x * blockDim.x + threadIdx.x;
    if (g >= ngroups) return;

    const float4* s4 = (const float4*)(src + (size_t)g * 16);
    float in[16];
    float4 x0 = s4[0], x1 = s4[1], x2 = s4[2], x3 = s4[3];
    in[0]=x0.x; in[1]=x0.y; in[2]=x0.z; in[3]=x0.w;
    in[4]=x1.x; in[5]=x1.y; in[6]=x1.z; in[7]=x1.w;
    in[8]=x2.x; in[9]=x2.y; in[10]=x2.z; in[11]=x2.w;
    in[12]=x3.x; in[13]=x3.y; in[14]=x3.z; in[15]=x3.w;

    float h[16], l[16];
#pragma unroll
    for (int i = 0; i < 16; i++) {
        h[i] = __uint_as_float(f2tf32(in[i]));
        l[i] = in[i] - h[i];
    }

    // fp32 hi, permuted per 8: phys j holds logical {0,4,1,5,2,6,3,7}[j]
    float4 o0 = {h[0], h[4], h[1], h[5]};
    float4 o1 = {h[2], h[6], h[3], h[7]};
    float4 o2 = {h[8], h[12], h[9], h[13]};
    float4 o3 = {h[10], h[14], h[11], h[15]};
    float4* d4 = (float4*)(hi32 + (size_t)g * 16);
    d4[0] = o0; d4[1] = o1; d4[2] = o2; d4[3] = o3;

    // bf16 pairs (P_j = k{2j,2j+1}), phys pair order {0,4,1,5,2,6,3,7}
    const int pp[8] = {0, 4, 1, 5, 2, 6, 3, 7};
    __nv_bfloat162 wh[8], wl[8];
#pragma unroll
    for (int j = 0; j < 8; j++) {
        int p = pp[j];
        wh[j] = __floats2bfloat162_rn(h[2 * p], h[2 * p + 1]);
        wl[j] = __floats2bfloat162_rn(l[2 * p], l[2 * p + 1]);
    }
    uint4* dh = (uint4*)(hibf + (size_t)g * 16);
    uint4* dl = (uint4*)(lobf + (size_t)g * 16);
    dh[0] = *(uint4*)&wh[0]; dh[1] = *(uint4*)&wh[4];
    dl[0] = *(uint4*)&wl[0]; dl[1] = *(uint4*)&wl[4];
}

// ---------------------------------------------------------------------------
// 10*||p_m||^2, one warp per row
// ---------------------------------------------------------------------------
__global__ void psq_kernel(const float* __restrict__ B) {
    int w = (blockIdx.x * blockDim.x + threadIdx.x) >> 5;
    int lane = threadIdx.x & 31;
    if (w >= M_PROTO) return;
    const float4* row = (const float4*)(B + (size_t)w * K_DIM);
    float s = 0.f;
#pragma unroll
    for (int i = 0; i < 4; i++) {
        float4 v = row[lane + i * 32];
        s += v.x * v.x + v.y * v.y + v.z * v.z + v.w * v.w;
    }
#pragma unroll
    for (int o = 16; o > 0; o >>= 1) s += __shfl_xor_sync(0xFFFFFFFFu, s, o);
    if (lane == 0) g_psq10[w] = 10.f * s;
}

// ---------------------------------------------------------------------------
// GEMM: S[n,m] = 20 * dot(feat_n, proto_m) - 10*||p_m||^2
// Hybrid emulation: hi*hi in tf32 (exact), cross terms hi*lo + lo*hi in bf16.
// CTA 128x128, BK=16, 3-stage cp.async ring (one sync/iter, load-before-
// compute), 2 CTAs/SM.
// Per-stage layout (words): A32[0,2048) B32[2048,4096)
//   Ahibf[4096,5120) Alobf[5120,6144) Bhibf[6144,7168) Blobf[7168,8192)
// ---------------------------------------------------------------------------
#define STAGE_W   8192
#define N_STG     3
#define SMEM_TOT  (N_STG * STAGE_W * 4)   // 98304 bytes
#define KT_STEPS  (K_DIM / 16)            // 32

__global__ __launch_bounds__(256, 2)
void gemm_tc_kernel(float* __restrict__ S) {
    extern __shared__ float smem[];
    const uint32_t smem_base = smem_u32(smem);
    const int tid  = threadIdx.x;
    const int wid  = tid >> 5;
    const int lane = tid & 31;
    const int warpM = wid & 1;            // 2 warps in M (feat)
    const int warpN = wid >> 1;           // 4 warps in N (proto)
    const int m0 = blockIdx.x * 128;
    const int n0 = blockIdx.y * 128;

    float acc[4][4][4];
#pragma unroll
    for (int i = 0; i < 4; i++)
#pragma unroll
        for (int j = 0; j < 4; j++)
#pragma unroll
            for (int q = 0; q < 4; q++) acc[i][j][q] = 0.f;

    // ---- stage loader: 8 cp.async(16B) per thread ----
    auto load_stage = [&](int buf, int kt) {
        uint32_t sb = smem_base + (uint32_t)buf * (STAGE_W * 4);
#pragma unroll
        for (int it = 0; it < 8; it++) {
            int chunk = tid + it * 256;
            if (it < 2) {
                int c = chunk;                       // A hi32: 512 chunks
                int row = c >> 2, j = c & 3;
                uint32_t dst = sb + (uint32_t)(row * 16 + ((j ^ (row & 3)) << 2)) * 4u;
                const float* src = gAhi32 + (size_t)(n0 + row) * K_DIM + kt * 16 + j * 4;
                CP_ASYNC16(dst, src);
            } else if (it < 4) {
                int c = chunk - 512;                 // B hi32: 512 chunks
                int row = c >> 2, j = c & 3;
                uint32_t dst = sb + (uint32_t)(2048 + row * 16 + ((j ^ (row & 3)) << 2)) * 4u;
                const float* src = gBhi32 + (size_t)(m0 + row) * K_DIM + kt * 16 + j * 4;
                CP_ASYNC16(dst, src);
            } else {
                int arr = (chunk - 1024) >> 8;       // 0:Ahibf 1:Alobf 2:Bhibf 3:Blobf
                int cc  = (chunk - 1024) & 255;      // 0..255
                int row = cc >> 1, j = cc & 1;
                uint32_t dst = sb + (uint32_t)(4096 + arr * 1024 + row * 8 + j * 4) * 4u;
                const char* srcb;
                if (arr == 0)
                    srcb = (const char*)gAhibf + ((size_t)(n0 + row) * K_DIM + kt * 16) * 2 + j * 16;
                else if (arr == 1)
                    srcb = (const char*)gAlobf + ((size_t)(n0 + row) * K_DIM + kt * 16) * 2 + j * 16;
                else if (arr == 2)
                    srcb = (const char*)gBhibf + ((size_t)(m0 + row) * K_DIM + kt * 16) * 2 + j * 16;
                else
                    srcb = (const char*)gBlobf + ((size_t)(m0 + row) * K_DIM + kt * 16) * 2 + j * 16;
                CP_ASYNC16(dst, srcb);
            }
        }
        CP_COMMIT();
    };

    load_stage(0, 0);
    load_stage(1, 1);

    const int r  = lane >> 2;
    const int c2 = (lane & 3) * 2;

    int buf = 0;
    for (int kt = 0; kt < KT_STEPS; kt++) {
        CP_WAIT(1);
        __syncthreads();
        // issue next loads FIRST: they run concurrently with the MMA block.
        // Buffer (kt+2)%3 == (kt-1)%3, whose compute all warps finished
        // before arriving at the barrier above.
        if (kt + 2 < KT_STEPS) load_stage((buf + 2) % N_STG, kt + 2);

        const float* st   = smem + buf * STAGE_W;
        const float* sA32 = st;
        const float* sB32 = st + 2048;
        const float* sAh  = st + 4096;
        const float* sAl  = st + 5120;
        const float* sBh  = st + 6144;
        const float* sBl  = st + 7168;

        // ---- bf16 cross terms (full k16 in one mma each) ----
        uint2 BHb[4], BLb[4];
#pragma unroll
        for (int nt = 0; nt < 4; nt++) {
            int col = warpN * 32 + nt * 8 + r;
            BHb[nt] = *(const uint2*)(sBh + col * 8 + c2);
            BLb[nt] = *(const uint2*)(sBl + col * 8 + c2);
        }
#pragma unroll
        for (int mt = 0; mt < 4; mt++) {
            int row = warpM * 64 + mt * 16 + r;
            uint2 ah0 = *(const uint2*)(sAh + row * 8 + c2);
            uint2 ah1 = *(const uint2*)(sAh + (row + 8) * 8 + c2);
            uint2 al0 = *(const uint2*)(sAl + row * 8 + c2);
            uint2 al1 = *(const uint2*)(sAl + (row + 8) * 8 + c2);
#pragma unroll
            for (int nt = 0; nt < 4; nt++) {
                mma_bf16(acc[mt][nt], ah0.x, ah1.x, ah0.y, ah1.y, BLb[nt].x, BLb[nt].y);
                mma_bf16(acc[mt][nt], al0.x, al1.x, al0.y, al1.y, BHb[nt].x, BHb[nt].y);
            }
        }

        // ---- tf32 hi*hi (two k8 steps) ----
#pragma unroll
        for (int ko = 0; ko < 2; ko++) {
            const int kb = ko * 8 + c2;
            uint2 BH[4];
#pragma unroll
            for (int nt = 0; nt < 4; nt++) {
                int col = warpN * 32 + nt * 8 + r;
                BH[nt] = *(const uint2*)(sB32 + idx32(col, kb));
            }
#pragma unroll
            for (int mt = 0; mt < 4; mt++) {
                int row = warpM * 64 + mt * 16 + r;
                uint2 a0 = *(const uint2*)(sA32 + idx32(row, kb));
                uint2 a1 = *(const uint2*)(sA32 + idx32(row + 8, kb));
#pragma unroll
                for (int nt = 0; nt < 4; nt++)
                    mma_tf32(acc[mt][nt], a0.x, a1.x, a0.y, a1.y, BH[nt].x, BH[nt].y);
            }
        }

        buf = (buf + 1) % N_STG;
    }

    // ---- epilogue ----
    float* sp = smem;
    __syncthreads();
    if (tid < 128) sp[tid] = g_psq10[m0 + tid];
    __syncthreads();

#pragma unroll
    for (int mt = 0; mt < 4; mt++) {
        int gr = n0 + warpM * 64 + mt * 16 + r;
#pragma unroll
        for (int nt = 0; nt < 4; nt++) {
            int lc = warpN * 32 + nt * 8 + c2;
            float p0 = sp[lc], p1 = sp[lc + 1];
            float2 o0, o1;
            o0.x = 20.f * acc[mt][nt][0] - p0;
            o0.y = 20.f * acc[mt][nt][1] - p1;
            o1.x = 20.f * acc[mt][nt][2] - p0;
            o1.y = 20.f * acc[mt][nt][3] - p1;
            *(float2*)(S + (size_t)gr * M_PROTO + m0 + lc) = o0;
            *(float2*)(S + (size_t)(gr + 8) * M_PROTO + m0 + lc) = o1;
        }
    }
}

// ---------------------------------------------------------------------------
// Row softmax (in place), quality = 1/sum(exp), max_id = first argmax
// ---------------------------------------------------------------------------
__global__ void softmax_kernel(float* __restrict__ S,
                               float* __restrict__ quality,
                               float* __restrict__ maxid) {
    const int row = blockIdx.x;
    float* srow = S + (size_t)row * M_PROTO;
    const int t = threadIdx.x;

    float v[8];
    float4 v0 = *(const float4*)(srow + t * 8 + 0);
    float4 v1 = *(const float4*)(srow + t * 8 + 4);
    v[0] = v0.x; v[1] = v0.y; v[2] = v0.z; v[3] = v0.w;
    v[4] = v1.x; v[5] = v1.y; v[6] = v1.z; v[7] = v1.w;

    float lmax = v[0];
    int   limx = t * 8;
#pragma unroll
    for (int j = 1; j < 8; j++)
        if (v[j] > lmax) { lmax = v[j]; limx = t * 8 + j; }

    __shared__ float smax[256];
    __shared__ int   sidx[256];
    smax[t] = lmax;
    sidx[t] = limx;
    __syncthreads();
#pragma unroll
    for (int s = 128; s > 0; s >>= 1) {
        if (t < s) {
            float v2 = smax[t + s];
            int   i2 = sidx[t + s];
            if (v2 > smax[t] || (v2 == smax[t] && i2 < sidx[t])) {
                smax[t] = v2; sidx[t] = i2;
            }
        }
        __syncthreads();
    }
    const float rowmax = smax[0];
    const int   rowarg = sidx[0];
    __syncthreads();

    float e[8];
    float lsum = 0.f;
#pragma unroll
    for (int j = 0; j < 8; j++) { e[j] = expf(v[j] - rowmax); lsum += e[j]; }
    smax[t] = lsum;
    __syncthreads();
#pragma unroll
    for (int s = 128; s > 0; s >>= 1) {
        if (t < s) smax[t] += smax[t + s];
        __syncthreads();
    }
    const float inv = 1.0f / smax[0];

    float4 o0, o1;
    o0.x = e[0] * inv; o0.y = e[1] * inv; o0.z = e[2] * inv; o0.w = e[3] * inv;
    o1.x = e[4] * inv; o1.y = e[5] * inv; o1.z = e[6] * inv; o1.w = e[7] * inv;
    *(float4*)(srow + t * 8 + 0) = o0;
    *(float4*)(srow + t * 8 + 4) = o1;

    if (t == 0) {
        quality[row] = inv;
        maxid[row]   = (float)rowarg;
    }
}

// ---------------------------------------------------------------------------
extern "C" void kernel_launch(void* const* d_in, const int* in_sizes, int n_in,
                              void* d_out, int out_size) {
    const float* feat  = (const float*)d_in[0];   // [32768, 512]
    const float* proto = (const float*)d_in[1];   // [2048, 512]
    float* out = (float*)d_out;

    float* quality = out;
    float* maxid   = out + N_FEAT;
    float* pred    = out + 2 * N_FEAT;

    cudaFuncSetAttribute(gemm_tc_kernel,
                         cudaFuncAttributeMaxDynamicSharedMemorySize, SMEM_TOT);

    int gA = N_FEAT * K_DIM / 16;
    int gB = M_PROTO * K_DIM / 16;
    split_kernel<<<(gA + 255) / 256, 256>>>(feat, gA, 0);
    split_kernel<<<(gB + 255) / 256, 256>>>(proto, gB, 1);
    psq_kernel<<<M_PROTO / 8, 256>>>(proto);

    dim3 grid(M_PROTO / 128, N_FEAT / 128);
    gemm_tc_kernel<<<grid, 256, SMEM_TOT>>>(pred);

    softmax_kernel<<<N_FEAT, 256>>>(pred, quality, maxid);
}

// round 7
// speedup vs baseline: 1.0180x; 1.0180x over previous
#include <cuda_runtime.h>
#include <cuda_bf16.h>
#include <math.h>
#include <stdint.h>

// Problem shape (fixed by setup_inputs)
#define N_FEAT  32768
#define M_PROTO 2048
#define K_DIM   512

// ---------------------------------------------------------------------------
// Static device scratch (no cudaMalloc allowed)
// gXhi32: tf32-valued fp32, k-permuted per 8 (phys j = logical {0,4,1,5,2,6,3,7})
// gXhibf/gXlobf: bf16 hi/lo, pair-permuted per 8 pairs (same perm on pair idx)
// ---------------------------------------------------------------------------
__device__ float         gAhi32[(size_t)N_FEAT * K_DIM];
__device__ float         gBhi32[(size_t)M_PROTO * K_DIM];
__device__ __nv_bfloat16 gAhibf[(size_t)N_FEAT * K_DIM];
__device__ __nv_bfloat16 gAlobf[(size_t)N_FEAT * K_DIM];
__device__ __nv_bfloat16 gBhibf[(size_t)M_PROTO * K_DIM];
__device__ __nv_bfloat16 gBlobf[(size_t)M_PROTO * K_DIM];
__device__ float g_psq10[M_PROTO];      // 10 * ||p_m||^2

// ---------------------------------------------------------------------------
__device__ __forceinline__ uint32_t smem_u32(const void* p) {
    uint32_t a;
    asm("{ .reg .u64 t; cvta.to.shared.u64 t, %1; cvt.u32.u64 %0, t; }" : "=r"(a) : "l"(p));
    return a;
}
#define CP_ASYNC16(dst, src) \
    asm volatile("cp.async.cg.shared.global [%0], [%1], 16;" :: "r"(dst), "l"(src) : "memory")
#define CP_COMMIT() asm volatile("cp.async.commit_group;" ::: "memory")
#define CP_WAIT(n)  asm volatile("cp.async.wait_group %0;" :: "n"(n) : "memory")

__device__ __forceinline__ uint32_t f2tf32(float x) {
    uint32_t r;
    asm("cvt.rna.tf32.f32 %0, %1;" : "=r"(r) : "f"(x));
    return r;
}

// mma.sync m16n8k8 tf32 (sm_80 baseline -> legal on plain sm_100)
__device__ __forceinline__ void mma_tf32(float* d,
                                         uint32_t a0, uint32_t a1, uint32_t a2, uint32_t a3,
                                         uint32_t b0, uint32_t b1) {
    asm volatile(
        "mma.sync.aligned.m16n8k8.row.col.f32.tf32.tf32.f32 "
        "{%0,%1,%2,%3}, {%4,%5,%6,%7}, {%8,%9}, {%0,%1,%2,%3};"
        : "+f"(d[0]), "+f"(d[1]), "+f"(d[2]), "+f"(d[3])
        : "r"(a0), "r"(a1), "r"(a2), "r"(a3), "r"(b0), "r"(b1));
}

// mma.sync m16n8k16 bf16 (sm_80 baseline)
__device__ __forceinline__ void mma_bf16(float* d,
                                         uint32_t a0, uint32_t a1, uint32_t a2, uint32_t a3,
                                         uint32_t b0, uint32_t b1) {
    asm volatile(
        "mma.sync.aligned.m16n8k16.row.col.f32.bf16.bf16.f32 "
        "{%0,%1,%2,%3}, {%4,%5,%6,%7}, {%8,%9}, {%0,%1,%2,%3};"
        : "+f"(d[0]), "+f"(d[1]), "+f"(d[2]), "+f"(d[3])
        : "r"(a0), "r"(a1), "r"(a2), "r"(a3), "r"(b0), "r"(b1));
}

// ---------------------------------------------------------------------------
// Split fp32 -> tf32 hi (fp32, permuted per 8) + bf16(hi), bf16(lo)
// (pair-permuted per 8 pairs). One thread = 16 consecutive k of one row.
// ---------------------------------------------------------------------------
__global__ void split_kernel(const float* __restrict__ src, int ngroups, int which) {
    float*         hi32 = which ? gBhi32 : gAhi32;
    __nv_bfloat16* hibf = which ? gBhibf : gAhibf;
    __nv_bfloat16* lobf = which ? gBlobf : gAlobf;
    int g = blockIdx.x * blockDim.x + threadIdx.x;
    if (g >= ngroups) return;

    const float4* s4 = (const float4*)(src + (size_t)g * 16);
    float in[16];
    float4 x0 = s4[0], x1 = s4[1], x2 = s4[2], x3 = s4[3];
    in[0]=x0.x; in[1]=x0.y; in[2]=x0.z; in[3]=x0.w;
    in[4]=x1.x; in[5]=x1.y; in[6]=x1.z; in[7]=x1.w;
    in[8]=x2.x; in[9]=x2.y; in[10]=x2.z; in[11]=x2.w;
    in[12]=x3.x; in[13]=x3.y; in[14]=x3.z; in[15]=x3.w;

    float h[16], l[16];
#pragma unroll
    for (int i = 0; i < 16; i++) {
        h[i] = __uint_as_float(f2tf32(in[i]));
        l[i] = in[i] - h[i];
    }

    // fp32 hi, permuted per 8: phys j holds logical {0,4,1,5,2,6,3,7}[j]
    float4 o0 = {h[0], h[4], h[1], h[5]};
    float4 o1 = {h[2], h[6], h[3], h[7]};
    float4 o2 = {h[8], h[12], h[9], h[13]};
    float4 o3 = {h[10], h[14], h[11], h[15]};
    float4* d4 = (float4*)(hi32 + (size_t)g * 16);
    d4[0] = o0; d4[1] = o1; d4[2] = o2; d4[3] = o3;

    // bf16 pairs (P_j = k{2j,2j+1}), phys pair order {0,4,1,5,2,6,3,7}
    const int pp[8] = {0, 4, 1, 5, 2, 6, 3, 7};
    __nv_bfloat162 wh[8], wl[8];
#pragma unroll
    for (int j = 0; j < 8; j++) {
        int p = pp[j];
        wh[j] = __floats2bfloat162_rn(h[2 * p], h[2 * p + 1]);
        wl[j] = __floats2bfloat162_rn(l[2 * p], l[2 * p + 1]);
    }
    uint4* dh = (uint4*)(hibf + (size_t)g * 16);
    uint4* dl = (uint4*)(lobf + (size_t)g * 16);
    dh[0] = *(uint4*)&wh[0]; dh[1] = *(uint4*)&wh[4];
    dl[0] = *(uint4*)&wl[0]; dl[1] = *(uint4*)&wl[4];
}

// ---------------------------------------------------------------------------
// 10*||p_m||^2, one warp per row
// ---------------------------------------------------------------------------
__global__ void psq_kernel(const float* __restrict__ B) {
    int w = (blockIdx.x * blockDim.x + threadIdx.x) >> 5;
    int lane = threadIdx.x & 31;
    if (w >= M_PROTO) return;
    const float4* row = (const float4*)(B + (size_t)w * K_DIM);
    float s = 0.f;
#pragma unroll
    for (int i = 0; i < 4; i++) {
        float4 v = row[lane + i * 32];
        s += v.x * v.x + v.y * v.y + v.z * v.z + v.w * v.w;
    }
#pragma unroll
    for (int o = 16; o > 0; o >>= 1) s += __shfl_xor_sync(0xFFFFFFFFu, s, o);
    if (lane == 0) g_psq10[w] = 10.f * s;
}

// ---------------------------------------------------------------------------
// GEMM: S[n,m] = 20 * dot(feat_n, proto_m) - 10*||p_m||^2
// Hybrid emulation: hi*hi in tf32 (exact), cross terms hi*lo + lo*hi in bf16.
// CTA 128x128, BK=32 (16 iterations), 2-stage cp.async ring, occ=1,
// register-double-buffered fragments: every LDS batch is issued while the
// previous batch's MMAs execute, hiding fragment-load latency.
// Stage layout (words): A32[0,4096) B32[4096,8192)
//   Ahibf[8192,10240) Alobf[10240,12288) Bhibf[12288,14336) Blobf[14336,16384)
// ---------------------------------------------------------------------------
#define STAGE_W   16384
#define SMEM_TOT  (2 * STAGE_W * 4)       // 131072 bytes
#define KT_STEPS  (K_DIM / 32)            // 16

// fp32 tile word index (stride 32, granule-4 XOR swizzle, conflict-free)
__device__ __forceinline__ int w32(int row, int kb) {
    return row * 32 + ((((kb >> 2) ^ ((row & 3) << 1)) & 7) << 2) + (kb & 3);
}
// bf16 tile word index (stride 16 words, granule-8 XOR swizzle, conflict-free)
__device__ __forceinline__ int wbf(int row, int off) {
    return row * 16 + (off ^ ((row & 2) << 2));
}

__global__ __launch_bounds__(256, 1)
void gemm_tc_kernel(float* __restrict__ S) {
    extern __shared__ float smem[];
    const uint32_t smem_base = smem_u32(smem);
    const int tid  = threadIdx.x;
    const int wid  = tid >> 5;
    const int lane = tid & 31;
    const int warpM = wid & 1;            // 2 warps in M (feat)
    const int warpN = wid >> 1;           // 4 warps in N (proto)
    const int m0 = blockIdx.x * 128;
    const int n0 = blockIdx.y * 128;

    float acc[4][4][4];
#pragma unroll
    for (int i = 0; i < 4; i++)
#pragma unroll
        for (int j = 0; j < 4; j++)
#pragma unroll
            for (int q = 0; q < 4; q++) acc[i][j][q] = 0.f;

    // ---- stage loader: 16 cp.async(16B) per thread ----
    auto load_stage = [&](int buf, int kt) {
        uint32_t sb = smem_base + (uint32_t)buf * (STAGE_W * 4);
#pragma unroll
        for (int it = 0; it < 16; it++) {
            int chunk = tid + it * 256;
            if (it < 4) {
                int c = chunk;                       // A32: 1024 chunks
                int row = c >> 3, j = c & 7;
                uint32_t dst = sb + (uint32_t)(row * 32 + ((j ^ ((row & 3) << 1)) << 2)) * 4u;
                const float* src = gAhi32 + (size_t)(n0 + row) * K_DIM + kt * 32 + j * 4;
                CP_ASYNC16(dst, src);
            } else if (it < 8) {
                int c = chunk - 1024;                // B32: 1024 chunks
                int row = c >> 3, j = c & 7;
                uint32_t dst = sb + (uint32_t)(4096 + row * 32 + ((j ^ ((row & 3) << 1)) << 2)) * 4u;
                const float* src = gBhi32 + (size_t)(m0 + row) * K_DIM + kt * 32 + j * 4;
                CP_ASYNC16(dst, src);
            } else {
                int idx = chunk - 2048;              // bf16: 4 tiles x 512 chunks
                int arr = idx >> 9;                  // 0:Ahibf 1:Alobf 2:Bhibf 3:Blobf
                int cc  = idx & 511;
                int row = cc >> 2, j = cc & 3;
                uint32_t dst = sb + (uint32_t)(8192 + arr * 2048 + row * 16 +
                                               ((j << 2) ^ ((row & 2) << 2))) * 4u;
                const char* srcb;
                if (arr == 0)
                    srcb = (const char*)gAhibf + ((size_t)(n0 + row) * K_DIM + kt * 32) * 2 + j * 16;
                else if (arr == 1)
                    srcb = (const char*)gAlobf + ((size_t)(n0 + row) * K_DIM + kt * 32) * 2 + j * 16;
                else if (arr == 2)
                    srcb = (const char*)gBhibf + ((size_t)(m0 + row) * K_DIM + kt * 32) * 2 + j * 16;
                else
                    srcb = (const char*)gBlobf + ((size_t)(m0 + row) * K_DIM + kt * 32) * 2 + j * 16;
                CP_ASYNC16(dst, srcb);
            }
        }
        CP_COMMIT();
    };

    const int r  = lane >> 2;
    const int c2 = (lane & 3) * 2;

    // fragment register buffers
    uint2 AHb[4][2], ALb[4][2], BHb[4], BLb[4];     // bf16 (one k16 half)
    uint2 TA0[2][4], TA1[2][4], TB[2][4];           // tf32 ping-pong

    auto LOAD_BF = [&](const float* st, int h) {
        const float* sAh = st + 8192;
        const float* sAl = st + 10240;
        const float* sBh = st + 12288;
        const float* sBl = st + 14336;
        const int off = h * 8 + c2;
#pragma unroll
        for (int nt = 0; nt < 4; nt++) {
            int col = warpN * 32 + nt * 8 + r;
            BHb[nt] = *(const uint2*)(sBh + wbf(col, off));
            BLb[nt] = *(const uint2*)(sBl + wbf(col, off));
        }
#pragma unroll
        for (int mt = 0; mt < 4; mt++) {
            int row = warpM * 64 + mt * 16 + r;
            AHb[mt][0] = *(const uint2*)(sAh + wbf(row, off));
            AHb[mt][1] = *(const uint2*)(sAh + wbf(row + 8, off));
            ALb[mt][0] = *(const uint2*)(sAl + wbf(row, off));
            ALb[mt][1] = *(const uint2*)(sAl + wbf(row + 8, off));
        }
    };
    auto LOAD_TF = [&](const float* st, int h, int ko, int set) {
        const float* sA32 = st;
        const float* sB32 = st + 4096;
        const int kb = h * 16 + ko * 8 + c2;
#pragma unroll
        for (int nt = 0; nt < 4; nt++) {
            int col = warpN * 32 + nt * 8 + r;
            TB[set][nt] = *(const uint2*)(sB32 + w32(col, kb));
        }
#pragma unroll
        for (int mt = 0; mt < 4; mt++) {
            int row = warpM * 64 + mt * 16 + r;
            TA0[set][mt] = *(const uint2*)(sA32 + w32(row, kb));
            TA1[set][mt] = *(const uint2*)(sA32 + w32(row + 8, kb));
        }
    };
    auto MMA_BF = [&]() {
#pragma unroll
        for (int mt = 0; mt < 4; mt++)
#pragma unroll
            for (int nt = 0; nt < 4; nt++) {
                mma_bf16(acc[mt][nt], AHb[mt][0].x, AHb[mt][1].x, AHb[mt][0].y, AHb[mt][1].y,
                         BLb[nt].x, BLb[nt].y);
                mma_bf16(acc[mt][nt], ALb[mt][0].x, ALb[mt][1].x, ALb[mt][0].y, ALb[mt][1].y,
                         BHb[nt].x, BHb[nt].y);
            }
    };
    auto MMA_TF = [&](int set) {
#pragma unroll
        for (int mt = 0; mt < 4; mt++)
#pragma unroll
            for (int nt = 0; nt < 4; nt++)
                mma_tf32(acc[mt][nt], TA0[set][mt].x, TA1[set][mt].x,
                         TA0[set][mt].y, TA1[set][mt].y, TB[set][nt].x, TB[set][nt].y);
    };

    // prologue
    load_stage(0, 0);
    load_stage(1, 1);
    CP_WAIT(1);
    __syncthreads();
    LOAD_BF(smem, 0);

    for (int kt = 0; kt < KT_STEPS; kt++) {
        const int b = kt & 1;
        const float* st = smem + b * STAGE_W;

        LOAD_TF(st, 0, 0, 0);  MMA_BF();          // phase 1
        LOAD_TF(st, 0, 1, 1);  MMA_TF(0);         // phase 2
        LOAD_BF(st, 1);        MMA_TF(1);         // phase 3
        LOAD_TF(st, 1, 0, 0);  MMA_BF();          // phase 4
        LOAD_TF(st, 1, 1, 1);  MMA_TF(0);         // phase 5
        // phase 6: stage switch
        if (kt + 1 < KT_STEPS) {
            CP_WAIT(0);                            // stage b^1 fully resident
            __syncthreads();                       // all warps done reading b
            if (kt + 2 < KT_STEPS) load_stage(b, kt + 2);
            LOAD_BF(smem + (b ^ 1) * STAGE_W, 0);
        }
        MMA_TF(1);
    }

    // ---- epilogue ----
    float* sp = smem;
    __syncthreads();
    if (tid < 128) sp[tid] = g_psq10[m0 + tid];
    __syncthreads();

#pragma unroll
    for (int mt = 0; mt < 4; mt++) {
        int gr = n0 + warpM * 64 + mt * 16 + r;
#pragma unroll
        for (int nt = 0; nt < 4; nt++) {
            int lc = warpN * 32 + nt * 8 + c2;
            float p0 = sp[lc], p1 = sp[lc + 1];
            float2 o0, o1;
            o0.x = 20.f * acc[mt][nt][0] - p0;
            o0.y = 20.f * acc[mt][nt][1] - p1;
            o1.x = 20.f * acc[mt][nt][2] - p0;
            o1.y = 20.f * acc[mt][nt][3] - p1;
            *(float2*)(S + (size_t)gr * M_PROTO + m0 + lc) = o0;
            *(float2*)(S + (size_t)(gr + 8) * M_PROTO + m0 + lc) = o1;
        }
    }
}

// ---------------------------------------------------------------------------
// Row softmax (in place), quality = 1/sum(exp), max_id = first argmax
// ---------------------------------------------------------------------------
__global__ void softmax_kernel(float* __restrict__ S,
                               float* __restrict__ quality,
                               float* __restrict__ maxid) {
    const int row = blockIdx.x;
    float* srow = S + (size_t)row * M_PROTO;
    const int t = threadIdx.x;

    float v[8];
    float4 v0 = *(const float4*)(srow + t * 8 + 0);
    float4 v1 = *(const float4*)(srow + t * 8 + 4);
    v[0] = v0.x; v[1] = v0.y; v[2] = v0.z; v[3] = v0.w;
    v[4] = v1.x; v[5] = v1.y; v[6] = v1.z; v[7] = v1.w;

    float lmax = v[0];
    int   limx = t * 8;
#pragma unroll
    for (int j = 1; j < 8; j++)
        if (v[j] > lmax) { lmax = v[j]; limx = t * 8 + j; }

    __shared__ float smax[256];
    __shared__ int   sidx[256];
    smax[t] = lmax;
    sidx[t] = limx;
    __syncthreads();
#pragma unroll
    for (int s = 128; s > 0; s >>= 1) {
        if (t < s) {
            float v2 = smax[t + s];
            int   i2 = sidx[t + s];
            if (v2 > smax[t] || (v2 == smax[t] && i2 < sidx[t])) {
                smax[t] = v2; sidx[t] = i2;
            }
        }
        __syncthreads();
    }
    const float rowmax = smax[0];
    const int   rowarg = sidx[0];
    __syncthreads();

    float e[8];
    float lsum = 0.f;
#pragma unroll
    for (int j = 0; j < 8; j++) { e[j] = expf(v[j] - rowmax); lsum += e[j]; }
    smax[t] = lsum;
    __syncthreads();
#pragma unroll
    for (int s = 128; s > 0; s >>= 1) {
        if (t < s) smax[t] += smax[t + s];
        __syncthreads();
    }
    const float inv = 1.0f / smax[0];

    float4 o0, o1;
    o0.x = e[0] * inv; o0.y = e[1] * inv; o0.z = e[2] * inv; o0.w = e[3] * inv;
    o1.x = e[4] * inv; o1.y = e[5] * inv; o1.z = e[6] * inv; o1.w = e[7] * inv;
    *(float4*)(srow + t * 8 + 0) = o0;
    *(float4*)(srow + t * 8 + 4) = o1;

    if (t == 0) {
        quality[row] = inv;
        maxid[row]   = (float)rowarg;
    }
}

// ---------------------------------------------------------------------------
extern "C" void kernel_launch(void* const* d_in, const int* in_sizes, int n_in,
                              void* d_out, int out_size) {
    const float* feat  = (const float*)d_in[0];   // [32768, 512]
    const float* proto = (const float*)d_in[1];   // [2048, 512]
    float* out = (float*)d_out;

    float* quality = out;
    float* maxid   = out + N_FEAT;
    float* pred    = out + 2 * N_FEAT;

    cudaFuncSetAttribute(gemm_tc_kernel,
                         cudaFuncAttributeMaxDynamicSharedMemorySize, SMEM_TOT);

    int gA = N_FEAT * K_DIM / 16;
    int gB = M_PROTO * K_DIM / 16;
    split_kernel<<<(gA + 255) / 256, 256>>>(feat, gA, 0);
    split_kernel<<<(gB + 255) / 256, 256>>>(proto, gB, 1);
    psq_kernel<<<M_PROTO / 8, 256>>>(proto);

    dim3 grid(M_PROTO / 128, N_FEAT / 128);
    gemm_tc_kernel<<<grid, 256, SMEM_TOT>>>(pred);

    softmax_kernel<<<N_FEAT, 256>>>(pred, quality, maxid);
}